// round 12
// baseline (speedup 1.0000x reference)
#include <cuda_runtime.h>
#include <cstdint>

// ThresholdDecision: out[b] = 1.0f iff indicator (x[b,l,2] > 0.5) has a run of
// 4 consecutive ones ending at l in [4, L-2].
//
// Model (R5-R9): dur ~= fixed overhead + burst-service epoch (weakly scaling
// with first-window bytes) + serial tail (negligible if P(second trip) small).
// Knee tuning: GROUP=5 (160-pos window, ~20/4096 rows take a 2nd trip) cuts
// burst traffic 17% vs GROUP=6. __ldcs = streaming evict-first (single-use).

#define B_ROWS 4096
#define L_LEN  4096
#define THRESH 0.5f

#define WARPS_PER_BLOCK 4
#define THREADS (WARPS_PER_BLOCK * 32)
#define NBLOCKS (B_ROWS / WARPS_PER_BLOCK)     // 1024
#define GROUP   5                              // chunks per iteration (160 pos)
#define NGROUPS ((L_LEN / 32) / GROUP)         // 25 full groups (4000 pos)
#define TAIL_BASE (NGROUPS * GROUP * 32)       // 4000: last 96 pos handled after
#define TAIL_CHUNKS ((L_LEN - TAIL_BASE) / 32) // 3

__global__ __launch_bounds__(THREADS)
void threshold_decision_kernel(const float* __restrict__ x,
                               float* __restrict__ out,
                               int size_ok) {
    const int row_id = blockIdx.x * WARPS_PER_BLOCK + (threadIdx.x >> 5);
    const int lane   = threadIdx.x & 31;
    const float* row = x + (size_t)row_id * (size_t)(L_LEN * 3);

    unsigned carry = 0;   // indicator bits for positions base-3..base-1
    float result = 0.0f;
    bool done = false;

    for (int g = 0; g < NGROUPS; ++g) {
        const int base0 = g * (GROUP * 32);

        // Front-batched independent streaming loads: MLP = GROUP = 5
        float v[GROUP];
        #pragma unroll
        for (int k = 0; k < GROUP; ++k)
            v[k] = __ldcs(&row[(base0 + k * 32 + lane) * 3 + 2]);

        unsigned e_any = 0;
        #pragma unroll
        for (int k = 0; k < GROUP; ++k) {
            const unsigned m = __ballot_sync(0xffffffffu, v[k] > THRESH);

            // m64 bit j corresponds to position base0 + 32k + j - 3
            const uint64_t m64 = ((uint64_t)m << 3) | (uint64_t)carry;
            carry = m >> 29;

            const uint64_t r = m64 & (m64 >> 1) & (m64 >> 2) & (m64 >> 3);
            unsigned e = (unsigned)r;          // bit j: 4-run ends at base0+32k+j

            if (g == 0 && k == 0)
                e &= 0xFFFFFFF0u;              // require run end >= 4

            e_any |= e;
        }

        if (e_any) { result = 1.0f; done = true; break; }  // warp-uniform
    }

    // Remaining 96 positions (4000..4095); run end must be <= L-2 (4094).
    if (!done) {
        #pragma unroll
        for (int k = 0; k < TAIL_CHUNKS; ++k) {
            const int base = TAIL_BASE + k * 32;
            const float v = __ldcs(&row[(base + lane) * 3 + 2]);
            const unsigned m = __ballot_sync(0xffffffffu, v > THRESH);
            const uint64_t m64 = ((uint64_t)m << 3) | (uint64_t)carry;
            carry = m >> 29;
            const uint64_t r = m64 & (m64 >> 1) & (m64 >> 2) & (m64 >> 3);
            unsigned e = (unsigned)r;
            if (k == TAIL_CHUNKS - 1) e &= 0x7FFFFFFFu;  // exclude end at L-1
            if (e) result = 1.0f;
        }
    }

    if (lane == 0) {
        if (!size_ok) result = 4444.0f;        // diagnostic: bad n_in/in_sizes
        out[row_id] = result;
    }
}

extern "C" void kernel_launch(void* const* d_in, const int* in_sizes, int n_in,
                              void* d_out, int out_size) {
    const float* x = (const float*)d_in[0];
    float* out = (float*)d_out;
    const long long expect = (long long)B_ROWS * L_LEN * 3;
    const int size_ok = (n_in >= 1) && ((long long)in_sizes[0] == expect) &&
                        (out_size == B_ROWS);
    threshold_decision_kernel<<<NBLOCKS, THREADS>>>(x, out, size_ok);
}

// round 13
// speedup vs baseline: 1.0196x; 1.0196x over previous
#include <cuda_runtime.h>
#include <cstdint>

// ThresholdDecision: out[b] = 1.0f iff indicator (x[b,l,2] > 0.5) has a run of
// 4 consecutive ones ending at l in [4, L-2].
//
// Model (R5-R12, validated): dur ~= fixed overhead + burst-service epoch
// (~0.14us per MB of first-window traffic) + serial tail (negligible while
// second-trip rows stay rare). GROUP=4: 128-pos window, 6.3MB burst, ~57/4096
// rows take a hidden 2nd trip. Grid 1024 x 128thr, __ldcs streaming loads.

#define B_ROWS 4096
#define L_LEN  4096
#define THRESH 0.5f

#define WARPS_PER_BLOCK 4
#define THREADS (WARPS_PER_BLOCK * 32)
#define NBLOCKS (B_ROWS / WARPS_PER_BLOCK)     // 1024
#define GROUP   4                              // chunks per iteration (128 pos)
#define NGROUPS ((L_LEN / 32) / GROUP)         // 32 (covers L exactly)

__global__ __launch_bounds__(THREADS)
void threshold_decision_kernel(const float* __restrict__ x,
                               float* __restrict__ out,
                               int size_ok) {
    const int row_id = blockIdx.x * WARPS_PER_BLOCK + (threadIdx.x >> 5);
    const int lane   = threadIdx.x & 31;
    const float* row = x + (size_t)row_id * (size_t)(L_LEN * 3);

    unsigned carry = 0;   // indicator bits for positions base-3..base-1
    float result = 0.0f;

    for (int g = 0; g < NGROUPS; ++g) {
        const int base0 = g * (GROUP * 32);

        // Front-batched independent streaming loads: MLP = GROUP = 4
        float v[GROUP];
        #pragma unroll
        for (int k = 0; k < GROUP; ++k)
            v[k] = __ldcs(&row[(base0 + k * 32 + lane) * 3 + 2]);

        unsigned e_any = 0;
        #pragma unroll
        for (int k = 0; k < GROUP; ++k) {
            const unsigned m = __ballot_sync(0xffffffffu, v[k] > THRESH);

            // m64 bit j corresponds to position base0 + 32k + j - 3
            const uint64_t m64 = ((uint64_t)m << 3) | (uint64_t)carry;
            carry = m >> 29;

            const uint64_t r = m64 & (m64 >> 1) & (m64 >> 2) & (m64 >> 3);
            unsigned e = (unsigned)r;          // bit j: 4-run ends at base0+32k+j

            if (g == 0 && k == 0)
                e &= 0xFFFFFFF0u;              // require run end >= 4
            if (g == NGROUPS - 1 && k == GROUP - 1)
                e &= 0x7FFFFFFFu;              // require run end <= L-2 (4094)

            e_any |= e;
        }

        if (e_any) { result = 1.0f; break; }   // ballot math -> warp-uniform
    }

    if (lane == 0) {
        if (!size_ok) result = 4444.0f;        // diagnostic: bad n_in/in_sizes
        out[row_id] = result;
    }
}

extern "C" void kernel_launch(void* const* d_in, const int* in_sizes, int n_in,
                              void* d_out, int out_size) {
    const float* x = (const float*)d_in[0];
    float* out = (float*)d_out;
    const long long expect = (long long)B_ROWS * L_LEN * 3;
    const int size_ok = (n_in >= 1) && ((long long)in_sizes[0] == expect) &&
                        (out_size == B_ROWS);
    threshold_decision_kernel<<<NBLOCKS, THREADS>>>(x, out, size_ok);
}